// round 17
// baseline (speedup 1.0000x reference)
#include <cuda_runtime.h>
#include <cuda_fp16.h>
#include <cstdint>
#include <cstddef>

// ---------------- problem constants ----------------
#define S_LEN   4096
#define HDIM    2048
#define NH      16
#define NKV     8
#define HD      128
#define QKV_N   4096
#define VOFF    3072                     // NH*HD + NKV*HD
#define ATT_SCALE 0.08838834764831845f   // 128^-0.5
#define EPS_RMS 1e-6f
#define LOG2E   1.4426950408889634f

// ---------------- scratch (device globals: allowed) ----------------
__device__ float g_qkv[(size_t)S_LEN * QKV_N];       // 64 MB
__device__ uint32_t g_af[(size_t)32 * 64 * 2048];    // 16 MB  A tiles (fp16 frags)
__device__ uint32_t g_bf[(size_t)64 * 32 * 2048];    // 16 MB  B tiles (fp16 frags)
__device__ uint32_t g_qf[(size_t)NH * 256 * 1024];   // 16 MB  Q frags [h][grp16][1024]
__device__ uint32_t g_kf[(size_t)NKV * 128 * 2048];  //  8 MB  K tiles (fp16 frags)
__device__ uint32_t g_vf[(size_t)NKV * 128 * 2048];  //  8 MB  V tiles (fp16 frags)

// ---------------- helpers ----------------
__device__ __forceinline__ uint32_t f2h2(float lo, float hi) {
    __half2 h = __floats2half2_rn(lo, hi);
    return *(uint32_t*)&h;
}

__device__ __forceinline__ float ex2f(float x) {
    float y;
    asm("ex2.approx.f32 %0, %1;" : "=f"(y) : "f"(x));
    return y;
}

// fp16 mma with fp32 accumulate: D(16x8) += A(16x16) * B(16x8)
__device__ __forceinline__ void mma16(float c[4], const uint32_t a[4], const uint32_t b[2]) {
    asm volatile(
        "mma.sync.aligned.m16n8k16.row.col.f32.f16.f16.f32 "
        "{%0,%1,%2,%3}, {%4,%5,%6,%7}, {%8,%9}, {%0,%1,%2,%3};"
        : "+f"(c[0]), "+f"(c[1]), "+f"(c[2]), "+f"(c[3])
        : "r"(a[0]), "r"(a[1]), "r"(a[2]), "r"(a[3]), "r"(b[0]), "r"(b[1]));
}

__device__ __forceinline__ void cpasync16(uint32_t saddr, const void* gptr) {
    asm volatile("cp.async.cg.shared.global [%0], [%1], 16;"
                 :: "r"(saddr), "l"(gptr));
}
#define CP_COMMIT() asm volatile("cp.async.commit_group;")
#define CP_WAIT1()  asm volatile("cp.async.wait_group 1;")
#define CP_WAIT2()  asm volatile("cp.async.wait_group 2;")

// ================= permute kernels (GEMM operands) ====
// Fragment conventions (m16n8k16, g = lane>>2, t2 = (lane&3)*2):
//  A-frag reg r: row = base + (r&1)*8 + g, k = kbase + (r>>1)*8 + t2, pair (k,k+1)
//  B-frag: b0 = (k = t2, t2+1, col g), b1 = (k = t2+8, t2+9, col g)

// A tiles: [M][K] -> [mb][kb][2048], o = ((ks*8 + mf)*32 + lane)*4 + r
__global__ void permA_kernel(const float* __restrict__ A, uint32_t* __restrict__ out,
                             int M, int K) {
    __shared__ float t[128 * 36];
    const int kb = blockIdx.x, mb = blockIdx.y, nkb = gridDim.x;
    const int tid = threadIdx.x;
#pragma unroll
    for (int p = 0; p < 4; p++) {
        int idx = tid + p * 256;
        int r = idx >> 3, c4 = (idx & 7) * 4;
        float4 v = *(const float4*)&A[(size_t)(mb * 128 + r) * K + kb * 32 + c4];
        *(float4*)&t[r * 36 + c4] = v;
    }
    __syncthreads();
    uint32_t* dst = out + ((size_t)mb * nkb + kb) * 2048;
#pragma unroll
    for (int q = 0; q < 2; q++) {
        int o = q * 1024 + tid * 4;
        int lane = (o >> 2) & 31, mf = (o >> 7) & 7, ks = o >> 10;
        int g = lane >> 2, t2 = (lane & 3) * 2;
        int rb = mf * 16 + g, kb2 = ks * 16 + t2;
        uint4 u;
        u.x = f2h2(t[rb * 36 + kb2],           t[rb * 36 + kb2 + 1]);
        u.y = f2h2(t[(rb + 8) * 36 + kb2],     t[(rb + 8) * 36 + kb2 + 1]);
        u.z = f2h2(t[rb * 36 + kb2 + 8],       t[rb * 36 + kb2 + 9]);
        u.w = f2h2(t[(rb + 8) * 36 + kb2 + 8], t[(rb + 8) * 36 + kb2 + 9]);
        *(uint4*)&dst[o] = u;
    }
}

// B tiles: [K][N] -> [kb][nb][2048], o = ((ks*8 + nf2)*32 + lane)*4 + jl*2 + kk2
__global__ void permB_kernel(const float* __restrict__ B, uint32_t* __restrict__ out,
                             int K, int N) {
    __shared__ float t[32 * 132];
    const int nb = blockIdx.x, kb = blockIdx.y, nnb = gridDim.x;
    const int tid = threadIdx.x;
#pragma unroll
    for (int p = 0; p < 4; p++) {
        int idx = tid + p * 256;
        int r = idx >> 5, c4 = (idx & 31) * 4;
        float4 v = *(const float4*)&B[(size_t)(kb * 32 + r) * N + nb * 128 + c4];
        *(float4*)&t[r * 132 + c4] = v;
    }
    __syncthreads();
    uint32_t* dst = out + ((size_t)kb * nnb + nb) * 2048;
#pragma unroll
    for (int q = 0; q < 2; q++) {
        int o = q * 1024 + tid * 4;
        uint32_t u[4];
#pragma unroll
        for (int e = 0; e < 4; e++) {
            int oe = o + e;
            int kk2 = oe & 1, jl = (oe >> 1) & 1;
            int lane = (oe >> 2) & 31;
            int nf2 = (oe >> 7) & 7, ks = oe >> 10;
            int g = lane >> 2, t2 = (lane & 3) * 2;
            int nf = 2 * nf2 + jl;
            int k = ks * 16 + kk2 * 8 + t2;
            int c = nf * 8 + g;
            u[e] = f2h2(t[k * 132 + c], t[(k + 1) * 132 + c]);
        }
        *(uint4*)&dst[o] = make_uint4(u[0], u[1], u[2], u[3]);
    }
}

// ================= fused RMSNorm + mRoPE + Q/K/V fragment emit =================
// grid (128 token-tiles, 32): y<16 Q head y; 16<=y<24 K head y-16; y>=24 V head y-24.
// One head x 32 tokens per CTA, 2 barriers.
__global__ __launch_bounds__(256, 4)
void nrqkv_kernel(const float* __restrict__ qkv, const int* __restrict__ positions,
                  const float* __restrict__ qw, const float* __restrict__ kw,
                  const float* __restrict__ cache,
                  uint32_t* __restrict__ qf, uint32_t* __restrict__ kf,
                  uint32_t* __restrict__ vf) {
    __shared__ float cs[32][64], sn[32][64];
    __shared__ float tile[32][132];
    const int tid = threadIdx.x;
    const int tb = blockIdx.x;
    const int y = blockIdx.y;
    const int tile0 = tb * 32;
    const int warp = tid >> 5, lane = tid & 31;

    if (y < 24) {
        // ---- cos/sin gather for this token tile ----
        for (int idx = tid; idx < 2048; idx += 256) {
            int ts = idx >> 6, i = idx & 63;
            int m3 = i % 3;
            int sec = (i < 60) ? ((m3 == 1) ? 1 : ((m3 == 2) ? 2 : 0)) : 0;
            int pos = positions[sec * S_LEN + tile0 + ts];
            cs[ts][i] = cache[(size_t)pos * HD + i];
            sn[ts][i] = cache[(size_t)pos * HD + 64 + i];
        }
        __syncthreads();

        const int h = y;                               // qkv col offset h*128 valid for q AND k
        const float* wnorm = (y < NH) ? qw : kw;
        const int dbase = lane * 4;
        const bool lo = (lane < 16);

#pragma unroll
        for (int it = 0; it < 4; it++) {
            int ts = warp + it * 8;
            const float* src = qkv + (size_t)(tile0 + ts) * QKV_N + h * HD;
            float4 xv = *(const float4*)(src + dbase);
            float x[4] = {xv.x, xv.y, xv.z, xv.w};
            float ss = x[0]*x[0] + x[1]*x[1] + x[2]*x[2] + x[3]*x[3];
#pragma unroll
            for (int o = 16; o > 0; o >>= 1)
                ss += __shfl_xor_sync(0xffffffffu, ss, o);
            float inv = rsqrtf(ss * (1.0f / HD) + EPS_RMS);
            float4 wv = *(const float4*)(wnorm + dbase);
            float nx[4] = {x[0]*inv*wv.x, x[1]*inv*wv.y, x[2]*inv*wv.z, x[3]*inv*wv.w};
            float out[4];
#pragma unroll
            for (int j = 0; j < 4; j++) {
                float partner = __shfl_xor_sync(0xffffffffu, nx[j], 16);
                int i2 = (dbase + j) & 63;
                float c = cs[ts][i2], si = sn[ts][i2];
                out[j] = lo ? (nx[j] * c - partner * si)
                            : (nx[j] * c + partner * si);
            }
            *(float4*)&tile[ts][dbase] = make_float4(out[0], out[1], out[2], out[3]);
        }
        __syncthreads();

        if (y < NH) {
            // Q A-fragments (scale pre-folded)
            const float CC = ATT_SCALE * LOG2E;
            int g = lane >> 2, t2 = (lane & 3) * 2;
            int kd = warp * 16 + t2;
#pragma unroll
            for (int grp = 0; grp < 2; grp++) {
                int row = grp * 16 + g;
                uint4 u;
                u.x = f2h2(tile[row][kd] * CC,         tile[row][kd + 1] * CC);
                u.y = f2h2(tile[row + 8][kd] * CC,     tile[row + 8][kd + 1] * CC);
                u.z = f2h2(tile[row][kd + 8] * CC,     tile[row][kd + 9] * CC);
                u.w = f2h2(tile[row + 8][kd + 8] * CC, tile[row + 8][kd + 9] * CC);
                *(uint4*)&qf[((size_t)h * 256 + tb * 2 + grp) * 1024 + tid * 4] = u;
            }
        } else {
            // K B-fragments
            int kv = y - NH;
            uint32_t* dst = kf + ((size_t)kv * 128 + tb) * 2048;
#pragma unroll
            for (int q = 0; q < 2; q++) {
                int o = q * 1024 + tid * 4;
                uint32_t u[4];
#pragma unroll
                for (int e = 0; e < 4; e++) {
                    int oe = o + e;
                    int kk2 = oe & 1, jl = (oe >> 1) & 1;
                    int l = (oe >> 2) & 31;
                    int jj = (oe >> 7) & 1, ks = oe >> 8;
                    int g2 = l >> 2, t22 = (l & 3) * 2;
                    int j = 2 * jj + jl;
                    int r = j * 8 + g2;
                    int d = ks * 16 + kk2 * 8 + t22;
                    u[e] = f2h2(tile[r][d], tile[r][d + 1]);
                }
                *(uint4*)&dst[o] = make_uint4(u[0], u[1], u[2], u[3]);
            }
        }
    } else {
        // ---- V fragments (no norm/rope) ----
        int kv = y - 24;
        for (int idx = tid * 4; idx < 32 * 128; idx += 1024) {
            int r = idx >> 7, c4 = idx & 127;
            *(float4*)&tile[r][c4] =
                *(const float4*)&qkv[(size_t)(tile0 + r) * QKV_N + VOFF + kv * HD + c4];
        }
        __syncthreads();
        uint32_t* dst = vf + ((size_t)kv * 128 + tb) * 2048;
#pragma unroll
        for (int q = 0; q < 2; q++) {
            int o = q * 1024 + tid * 4;
            uint32_t u[4];
#pragma unroll
            for (int e = 0; e < 4; e++) {
                int oe = o + e;
                int kk2 = oe & 1, jl = (oe >> 1) & 1;
                int l = (oe >> 2) & 31;
                int jj = (oe >> 7) & 7, ks = oe >> 10;
                int g2 = l >> 2, t22 = (l & 3) * 2;
                int jv = 2 * jj + jl;
                int d = jv * 8 + g2;
                int k = ks * 16 + kk2 * 8 + t22;
                u[e] = f2h2(tile[k][d], tile[k + 1][d]);
            }
            *(uint4*)&dst[o] = make_uint4(u[0], u[1], u[2], u[3]);
        }
    }
}

// ================= fp16 GEMM (mma.sync m16n8k16) on pre-permuted tiles ========
#define GEMM_SMEM_BYTES (3 * 4096 * 4)

__global__ __launch_bounds__(256, 2)
void gemm_h(const uint32_t* __restrict__ Af, const uint32_t* __restrict__ Bf,
            float* __restrict__ C, int M, int N, int K) {
    extern __shared__ uint32_t smg[];
    const int tid  = threadIdx.x;
    const int lane = tid & 31;
    const int warp = tid >> 5;
    const int wm = warp >> 2, wn = warp & 3;
    const int g = lane >> 2, t = lane & 3;
    const int mb = blockIdx.y, nb = blockIdx.x;
    const int nkb = K / 32, nnb = N / 128;
    const uint32_t sbase = (uint32_t)__cvta_generic_to_shared(smg);
    const uint32_t* Asrc = Af + (size_t)mb * nkb * 2048;

    auto issue = [&](int kb, int st) {
        uint32_t dst = sbase + (uint32_t)st * 16384;
        const uint32_t* a = Asrc + (size_t)kb * 2048;
        const uint32_t* b = Bf + ((size_t)kb * nnb + nb) * 2048;
#pragma unroll
        for (int p = 0; p < 2; p++) {
            int i = tid + p * 256;
            cpasync16(dst + i * 16, a + i * 4);
            cpasync16(dst + 8192 + i * 16, b + i * 4);
        }
    };

    issue(0, 0); CP_COMMIT();
    issue(1, 1); CP_COMMIT();

    float acc[4][4][4];
#pragma unroll
    for (int i = 0; i < 4; i++)
#pragma unroll
        for (int j = 0; j < 4; j++)
#pragma unroll
            for (int e = 0; e < 4; e++) acc[i][j][e] = 0.f;

    for (int kb = 0; kb < nkb; kb++) {
        CP_WAIT1();
        __syncthreads();
        if (kb + 2 < nkb) issue(kb + 2, (kb + 2) % 3);
        CP_COMMIT();

        const uint32_t* As = smg + (kb % 3) * 4096;
        const uint32_t* Bs = As + 2048;
#pragma unroll
        for (int ks = 0; ks < 2; ks++) {
            uint32_t a[4][4];
#pragma unroll
            for (int i = 0; i < 4; i++) {
                uint4 av = *(const uint4*)&As[((ks * 8 + wm * 4 + i) * 32 + lane) * 4];
                a[i][0] = av.x; a[i][1] = av.y; a[i][2] = av.z; a[i][3] = av.w;
            }
#pragma unroll
            for (int j2 = 0; j2 < 2; j2++) {
                uint4 bv = *(const uint4*)&Bs[((ks * 8 + wn * 2 + j2) * 32 + lane) * 4];
                uint32_t b0[2] = {bv.x, bv.y};
                uint32_t b1[2] = {bv.z, bv.w};
#pragma unroll
                for (int i = 0; i < 4; i++) {
                    mma16(acc[i][2 * j2],     a[i], b0);
                    mma16(acc[i][2 * j2 + 1], a[i], b1);
                }
            }
        }
    }

#pragma unroll
    for (int i = 0; i < 4; i++)
#pragma unroll
        for (int j = 0; j < 4; j++) {
            int row0 = mb * 128 + wm * 64 + i * 16 + g;
            int col  = nb * 128 + wn * 32 + j * 8 + 2 * t;
            *(float2*)&C[(size_t)row0 * N + col]       = make_float2(acc[i][j][0], acc[i][j][1]);
            *(float2*)&C[(size_t)(row0 + 8) * N + col] = make_float2(acc[i][j][2], acc[i][j][3]);
        }
}

// ================= fp16 flash attention, Bq=64/Bk=32 =================
#define ATTN_SMEM_BYTES (3 * 4096 * 4)

__global__ __launch_bounds__(128, 3)
void attn_h(const uint32_t* __restrict__ qf, const uint32_t* __restrict__ Kf,
            const uint32_t* __restrict__ Vf, uint32_t* __restrict__ af) {
    extern __shared__ uint32_t smu[];

    const int tid  = threadIdx.x;
    const int lane = tid & 31;
    const int w    = tid >> 5;           // 0..3
    const int g = lane >> 2, t = lane & 3;
    const int h  = blockIdx.y;
    const int qt = (int)gridDim.x - 1 - (int)blockIdx.x;   // heavy first
    const int q0 = qt * 64;
    const int kv = h >> 1;
    const int nkt = 2 * qt + 2;          // 32-wide key tiles
    const uint32_t sbase = (uint32_t)__cvta_generic_to_shared(smu);

    const uint32_t* Ksrc = Kf + (size_t)kv * (S_LEN / 32) * 2048;
    const uint32_t* Vsrc = Vf + (size_t)kv * (S_LEN / 32) * 2048;
    auto issue = [&](int kt, int st) {
        if (kt < nkt) {
            uint32_t dst = sbase + (uint32_t)st * 16384;
            const uint32_t* kp = Ksrc + (size_t)kt * 2048;
            const uint32_t* vp = Vsrc + (size_t)kt * 2048;
#pragma unroll
            for (int p = 0; p < 4; p++) {
                int i = tid + p * 128;
                cpasync16(dst + i * 16, kp + i * 4);
                cpasync16(dst + 8192 + i * 16, vp + i * 4);
            }
        }
    };
    issue(0, 0); CP_COMMIT();
    issue(1, 1); CP_COMMIT();
    issue(2, 2); CP_COMMIT();

    // ---- Q fragments: direct coalesced loads (overlap the cp.async fills) ----
    uint32_t aq[8][4];
    {
        const uint32_t* qsrc = qf + ((size_t)h * 256 + (q0 >> 4) + w) * 1024;
#pragma unroll
        for (int ks = 0; ks < 8; ks++) {
            uint4 v = *(const uint4*)&qsrc[(ks * 32 + lane) * 4];
            aq[ks][0] = v.x; aq[ks][1] = v.y; aq[ks][2] = v.z; aq[ks][3] = v.w;
        }
    }

    float oacc[16][4];
#pragma unroll
    for (int j = 0; j < 16; j++)
#pragma unroll
        for (int e = 0; e < 4; e++) oacc[j][e] = 0.f;
    float m2a = -1e30f, m2b = -1e30f;
    float la = 0.f, lb = 0.f;

    const int r0g = q0 + w * 16 + g;

#pragma unroll 1
    for (int kt = 0; kt < nkt; kt++) {
        CP_WAIT2();
        __syncthreads();
        const uint32_t* Ks = smu + (kt % 3) * 4096;
        const uint32_t* Vs = Ks + 2048;

        // ---- scores: 16 rows x 32 keys per warp ----
        float sc[4][4];
#pragma unroll
        for (int j = 0; j < 4; j++)
#pragma unroll
            for (int e = 0; e < 4; e++) sc[j][e] = 0.f;
#pragma unroll
        for (int ks = 0; ks < 8; ks++) {
#pragma unroll
            for (int jj = 0; jj < 2; jj++) {
                uint4 bv = *(const uint4*)&Ks[((ks * 2 + jj) * 32 + lane) * 4];
                uint32_t b0[2] = {bv.x, bv.y};
                uint32_t b1[2] = {bv.z, bv.w};
                mma16(sc[2 * jj],     aq[ks], b0);
                mma16(sc[2 * jj + 1], aq[ks], b1);
            }
        }

        // ---- causal mask (diagonal tiles only) ----
        if (kt >= 2 * qt) {
            const int k0 = kt * 32;
#pragma unroll
            for (int j = 0; j < 4; j++) {
                int c0 = k0 + j * 8 + 2 * t;
                if (c0     > r0g)     sc[j][0] = -1e30f;
                if (c0 + 1 > r0g)     sc[j][1] = -1e30f;
                if (c0     > r0g + 8) sc[j][2] = -1e30f;
                if (c0 + 1 > r0g + 8) sc[j][3] = -1e30f;
            }
        }

        // ---- online softmax (warp-local, quad reduction) ----
        float mx0 = -1e30f, mx1 = -1e30f;
#pragma unroll
        for (int j = 0; j < 4; j++) {
            mx0 = fmaxf(mx0, fmaxf(sc[j][0], sc[j][1]));
            mx1 = fmaxf(mx1, fmaxf(sc[j][2], sc[j][3]));
        }
        mx0 = fmaxf(mx0, __shfl_xor_sync(0xffffffffu, mx0, 1));
        mx0 = fmaxf(mx0, __shfl_xor_sync(0xffffffffu, mx0, 2));
        mx1 = fmaxf(mx1, __shfl_xor_sync(0xffffffffu, mx1, 1));
        mx1 = fmaxf(mx1, __shfl_xor_sync(0xffffffffu, mx1, 2));
        float mn0 = fmaxf(m2a, mx0), mn1 = fmaxf(m2b, mx1);
        float f0 = ex2f(m2a - mn0), f1 = ex2f(m2b - mn1);
        m2a = mn0; m2b = mn1;

        float s0 = 0.f, s1 = 0.f;
#pragma unroll
        for (int j = 0; j < 4; j++) {
            sc[j][0] = ex2f(sc[j][0] - mn0);
            sc[j][1] = ex2f(sc[j][1] - mn0);
            sc[j][2] = ex2f(sc[j][2] - mn1);
            sc[j][3] = ex2f(sc[j][3] - mn1);
            s0 += sc[j][0] + sc[j][1];
            s1 += sc[j][2] + sc[j][3];
        }
        s0 += __shfl_xor_sync(0xffffffffu, s0, 1);
        s0 += __shfl_xor_sync(0xffffffffu, s0, 2);
        s1 += __shfl_xor_sync(0xffffffffu, s1, 1);
        s1 += __shfl_xor_sync(0xffffffffu, s1, 2);
        la = la * f0 + s0;
        lb = lb * f1 + s1;

#pragma unroll
        for (int j = 0; j < 16; j++) {
            oacc[j][0] *= f0; oacc[j][1] *= f0;
            oacc[j][2] *= f1; oacc[j][3] *= f1;
        }

        // ---- P fragments directly from sc (no smem roundtrip) ----
        uint32_t pa[2][4];
#pragma unroll
        for (int ks2 = 0; ks2 < 2; ks2++) {
            pa[ks2][0] = f2h2(sc[2 * ks2][0],     sc[2 * ks2][1]);
            pa[ks2][1] = f2h2(sc[2 * ks2][2],     sc[2 * ks2][3]);
            pa[ks2][2] = f2h2(sc[2 * ks2 + 1][0], sc[2 * ks2 + 1][1]);
            pa[ks2][3] = f2h2(sc[2 * ks2 + 1][2], sc[2 * ks2 + 1][3]);
        }

        // ---- O += P @ V ----
#pragma unroll
        for (int ks2 = 0; ks2 < 2; ks2++) {
#pragma unroll
            for (int jj = 0; jj < 8; jj++) {
                uint4 bv = *(const uint4*)&Vs[((ks2 * 8 + jj) * 32 + lane) * 4];
                uint32_t b0[2] = {bv.x, bv.y};
                uint32_t b1[2] = {bv.z, bv.w};
                mma16(oacc[2 * jj],     pa[ks2], b0);
                mma16(oacc[2 * jj + 1], pa[ks2], b1);
            }
        }
        __syncthreads();          // all warps done with this stage
        issue(kt + 3, kt % 3);    // refill consumed stage
        CP_COMMIT();
    }

    // ---- epilogue: write O directly as O-proj A-fragment tiles ----
    {
        float inv0 = 1.f / la, inv1 = 1.f / lb;
        const int mb = q0 >> 7;
        const int mf = 4 * (qt & 1) + w;
#pragma unroll
        for (int jp = 0; jp < 8; jp++) {           // pairs (j=2jp, 2jp+1)
            int j = 2 * jp;
            int kb = h * 4 + (j >> 2);
            int ks = (j >> 1) & 1;
            uint32_t* dst = af + ((size_t)mb * 64 + kb) * 2048
                               + ((ks * 8 + mf) * 32 + lane) * 4;
            uint4 u;
            u.x = f2h2(oacc[j][0] * inv0,     oacc[j][1] * inv0);
            u.y = f2h2(oacc[j][2] * inv1,     oacc[j][3] * inv1);
            u.z = f2h2(oacc[j + 1][0] * inv0, oacc[j + 1][1] * inv0);
            u.w = f2h2(oacc[j + 1][2] * inv1, oacc[j + 1][3] * inv1);
            *(uint4*)dst = u;
        }
    }
}

// ---------------- launch ----------------
extern "C" void kernel_launch(void* const* d_in, const int* in_sizes, int n_in,
                              void* d_out, int out_size) {
    const float* hidden    = (const float*)d_in[0];
    const int*   positions = (const int*)  d_in[1];
    const float* w_qkv     = (const float*)d_in[2];
    const float* w_o       = (const float*)d_in[3];
    const float* q_norm_w  = (const float*)d_in[4];
    const float* k_norm_w  = (const float*)d_in[5];
    const float* cache     = (const float*)d_in[6];
    float* out = (float*)d_out;

    float *qkv_p;
    uint32_t *af_p, *bf_p, *qf_p, *kf_p, *vf_p;
    cudaGetSymbolAddress((void**)&qkv_p, g_qkv);
    cudaGetSymbolAddress((void**)&af_p,  g_af);
    cudaGetSymbolAddress((void**)&bf_p,  g_bf);
    cudaGetSymbolAddress((void**)&qf_p,  g_qf);
    cudaGetSymbolAddress((void**)&kf_p,  g_kf);
    cudaGetSymbolAddress((void**)&vf_p,  g_vf);

    cudaFuncSetAttribute(gemm_h, cudaFuncAttributeMaxDynamicSharedMemorySize,
                         GEMM_SMEM_BYTES);
    cudaFuncSetAttribute(attn_h, cudaFuncAttributeMaxDynamicSharedMemorySize,
                         ATTN_SMEM_BYTES);

    // 1) QKV projection (fp16 tensor cores)
    permA_kernel<<<dim3(64, 32), 256>>>(hidden, af_p, S_LEN, HDIM);
    permB_kernel<<<dim3(32, 64), 256>>>(w_qkv, bf_p, HDIM, QKV_N);
    gemm_h<<<dim3(32, 32), 256, GEMM_SMEM_BYTES>>>(af_p, bf_p, qkv_p,
                                                   S_LEN, QKV_N, HDIM);

    // 2) fused RMSNorm + mRoPE + Q/K/V fragment emit (one head per CTA)
    nrqkv_kernel<<<dim3(S_LEN / 32, 32), 256>>>(qkv_p, positions, q_norm_w,
                                                k_norm_w, cache, qf_p, kf_p, vf_p);

    // 3) flash attention (fp16) -> writes O as A-frag tiles into g_af
    attn_h<<<dim3(S_LEN / 64, NH), 128, ATTN_SMEM_BYTES>>>(qf_p, kf_p, vf_p, af_p);

    // 4) output projection (fp16 tensor cores)
    permB_kernel<<<dim3(16, 64), 256>>>(w_o, bf_p, HDIM, HDIM);
    gemm_h<<<dim3(16, 32), 256, GEMM_SMEM_BYTES>>>(af_p, bf_p, out,
                                                   S_LEN, HDIM, HDIM);
}